// round 4
// baseline (speedup 1.0000x reference)
#include <cuda_runtime.h>
#include <math.h>

#define FD 256

// -------- device scratch (zero-initialized at module load) --------
__device__ float g_dist[128 * 128];
__device__ float g_feat[128 * 128];
__device__ float g_md[128], g_fs[128], g_mf[128], g_mdist[128];
__device__ unsigned long long g_colkey_d[128], g_colkey_f[128];
__device__ float g_geo[512];
__device__ float g_h1[256];
__device__ unsigned g_ctr1, g_ctr2, g_flag;

// orderable uint mapping: ascending uint <=> ascending float
__device__ __forceinline__ unsigned f2o(float f) {
    unsigned u = __float_as_uint(f);
    return (u & 0x80000000u) ? ~u : (u | 0x80000000u);
}
// packed key: max over keys == max value, ties -> smallest index
__device__ __forceinline__ unsigned long long pk(float v, unsigned inv_idx) {
    return (((unsigned long long)f2o(v)) << 32) | (unsigned long long)inv_idx;
}
__device__ __forceinline__ unsigned vpoll(unsigned* p) {
    return *(volatile unsigned*)p;
}

__global__ void __launch_bounds__(256)
k_all(const float* __restrict__ pts, const float* __restrict__ trans,
      const float* __restrict__ ref_f, const float* __restrict__ src_f,
      const float* __restrict__ W1, const float* __restrict__ b1,
      const float* __restrict__ gm1, const float* __restrict__ bt1,
      const float* __restrict__ W2, const float* __restrict__ b2,
      const float* __restrict__ gm2, const float* __restrict__ bt2,
      const float* __restrict__ W3, const float* __restrict__ b3,
      float* __restrict__ out) {
    __shared__ float spx[256], spy[256], spz[256], ssq[256];
    __shared__ __align__(16) float sref[FD];
    __shared__ float sdrow[128], sfrow[128];
    __shared__ float sred[24], smax[8];
    __shared__ unsigned long long swd[4], swf[4];
    // block-0 phases
    __shared__ float smd[256], sfs[256], smf[256], smdist[256];
    __shared__ unsigned long long sk1[256], sk2[256];
    __shared__ __align__(16) float ha[256];
    __shared__ float h2s[128];
    __shared__ __align__(16) float h2a[128];

    const int t = threadIdx.x;
    const int i = blockIdx.x;
    const int w = t >> 5, lane = t & 31;

    // ===================== Phase 1: normalize + my row =====================
    sref[t] = __ldg(&ref_f[i * FD + t]);

    float tr0 = __ldg(&trans[0]), tr1 = __ldg(&trans[1]), tr2  = __ldg(&trans[2]),  tr3  = __ldg(&trans[3]);
    float tr4 = __ldg(&trans[4]), tr5 = __ldg(&trans[5]), tr6  = __ldg(&trans[6]),  tr7  = __ldg(&trans[7]);
    float tr8 = __ldg(&trans[8]), tr9 = __ldg(&trans[9]), tr10 = __ldg(&trans[10]), tr11 = __ldg(&trans[11]);

    // one point per thread; transform src half
    float px = pts[3 * t + 0];
    float py = pts[3 * t + 1];
    float pz = pts[3 * t + 2];
    if (t >= 128) {
        float x = tr0 * px + tr1 * py + tr2  * pz + tr3;
        float y = tr4 * px + tr5 * py + tr6  * pz + tr7;
        float z = tr8 * px + tr9 * py + tr10 * pz + tr11;
        px = x; py = y; pz = z;
    }
    float lx = px, ly = py, lz = pz;
#pragma unroll
    for (int o = 16; o > 0; o >>= 1) {
        lx += __shfl_xor_sync(0xffffffffu, lx, o);
        ly += __shfl_xor_sync(0xffffffffu, ly, o);
        lz += __shfl_xor_sync(0xffffffffu, lz, o);
    }
    if (lane == 0) { sred[w] = lx; sred[8 + w] = ly; sred[16 + w] = lz; }
    __syncthreads();
    float cx = 0.f, cy = 0.f, cz = 0.f;
#pragma unroll
    for (int q = 0; q < 8; q++) { cx += sred[q]; cy += sred[8 + q]; cz += sred[16 + q]; }
    cx *= (1.0f / 256.0f); cy *= (1.0f / 256.0f); cz *= (1.0f / 256.0f);

    px -= cx; py -= cy; pz -= cz;
    float sq = px * px + py * py + pz * pz;
    float lm = sq;
#pragma unroll
    for (int o = 16; o > 0; o >>= 1)
        lm = fmaxf(lm, __shfl_xor_sync(0xffffffffu, lm, o));
    if (lane == 0) smax[w] = lm;
    __syncthreads();
    float m2 = smax[0];
#pragma unroll
    for (int q = 1; q < 8; q++) m2 = fmaxf(m2, smax[q]);
    float inv = 1.0f / sqrtf(m2);
    spx[t] = px * inv; spy[t] = py * inv; spz[t] = pz * inv;
    ssq[t] = sq * inv * inv;
    __syncthreads();

    // dist entry (i, j=t) for t<128
    float e = 0.f;
    if (t < 128) {
        float rx = spx[i], ry = spy[i], rz = spz[i];
        int sj = 128 + t;
        float d = ssq[i] + ssq[sj] - 2.0f * (rx * spx[sj] + ry * spy[sj] + rz * spz[sj]);
        d = fmaxf(d, 0.0f);
        e = expf(-d);
        g_dist[i * 128 + t] = e;
        sdrow[t] = e;
        atomicMax(&g_colkey_d[t], pk(e, 127u - (unsigned)i));
    }

    // feat row: 8 warps x 16 src rows, coalesced
    {
        const float4* sr4 = reinterpret_cast<const float4*>(sref);
        float4 r0 = sr4[lane];
        float4 r1 = sr4[lane + 32];
        int jb = w * 16;
#pragma unroll 4
        for (int jj = 0; jj < 16; jj++) {
            int j = jb + jj;
            const float4* s4 = reinterpret_cast<const float4*>(src_f + (size_t)j * FD);
            float4 a0 = __ldg(&s4[lane]);
            float4 a1 = __ldg(&s4[lane + 32]);
            float acc = a0.x * r0.x + a0.y * r0.y + a0.z * r0.z + a0.w * r0.w
                      + a1.x * r1.x + a1.y * r1.y + a1.z * r1.z + a1.w * r1.w;
#pragma unroll
            for (int o = 16; o > 0; o >>= 1)
                acc += __shfl_xor_sync(0xffffffffu, acc, o);
            if (lane == 0) sfrow[j] = acc;
        }
    }
    __syncthreads();
    if (t < 128) {
        float fv = sfrow[t];
        g_feat[i * 128 + t] = fv;
        atomicMax(&g_colkey_f[t], pk(fv, 127u - (unsigned)i));
        unsigned long long kd = pk(e,  127u - (unsigned)t);
        unsigned long long kf = pk(fv, 127u - (unsigned)t);
#pragma unroll
        for (int o = 16; o > 0; o >>= 1) {
            unsigned long long od = __shfl_xor_sync(0xffffffffu, kd, o);
            unsigned long long of = __shfl_xor_sync(0xffffffffu, kf, o);
            if (od > kd) kd = od;
            if (of > kf) kf = of;
        }
        if (lane == 0) { swd[w] = kd; swf[w] = kf; }
    }
    __syncthreads();
    if (t == 0) {
        unsigned long long bd = swd[0], bf = swf[0];
#pragma unroll
        for (int q = 1; q < 4; q++) {
            if (swd[q] > bd) bd = swd[q];
            if (swf[q] > bf) bf = swf[q];
        }
        int jd = 127 - (int)(bd & 0xFFFFFFFFull);
        int jf = 127 - (int)(bf & 0xFFFFFFFFull);
        g_md[i]    = sdrow[jd];
        g_fs[i]    = sfrow[jd];
        g_mf[i]    = sfrow[jf];
        g_mdist[i] = sdrow[jf];
    }

    // ------- grid barrier #1 arrival -------
    __threadfence();
    __syncthreads();
    if (t == 0) atomicAdd(&g_ctr1, 1u);

    // ============ Phase 2a: block 0 assembles + rank-sorts -> g_geo =========
    if (i == 0) {
        if (t == 0) { while (vpoll(&g_ctr1) < 128u) {} }
        __syncthreads();
        __threadfence();

        if (t < 128) {
            smd[t]    = __ldcg(&g_md[t]);
            sfs[t]    = __ldcg(&g_fs[t]);
            smf[t]    = __ldcg(&g_mf[t]);
            smdist[t] = __ldcg(&g_mdist[t]);
        } else {
            int c = t - 128;
            unsigned long long kd = __ldcg(&g_colkey_d[c]);
            unsigned long long kf = __ldcg(&g_colkey_f[c]);
            int id = 127 - (int)(kd & 0xFFFFFFFFull);
            int jf = 127 - (int)(kf & 0xFFFFFFFFull);
            smd[t]    = __ldcg(&g_dist[id * 128 + c]);
            sfs[t]    = __ldcg(&g_feat[id * 128 + c]);
            smf[t]    = __ldcg(&g_feat[jf * 128 + c]);
            smdist[t] = __ldcg(&g_dist[jf * 128 + c]);
        }
        __syncthreads();

        unsigned long long k1 = pk(smd[t], 255u - (unsigned)t);
        unsigned long long k2 = pk(smf[t], 255u - (unsigned)t);
        sk1[t] = k1; sk2[t] = k2;
        __syncthreads();
        int r1 = 0, r2 = 0;
#pragma unroll 8
        for (int j = 0; j < 256; j++) {
            r1 += (sk1[j] > k1) ? 1 : 0;
            r2 += (sk2[j] > k2) ? 1 : 0;
        }
        g_geo[r1]       = smd[t] * sfs[t];
        g_geo[256 + r2] = smdist[t] * smf[t];
        __threadfence();
        __syncthreads();
        if (t == 0) *(volatile unsigned*)&g_flag = 1u;
    }

    // ============ Phase 2b: all blocks wait for geo, do 2 fc1 channels ======
    if (t == 0 && i != 0) { while (vpoll(&g_flag) == 0u) {} }
    __syncthreads();
    __threadfence();

    if (w < 2) {
        int c = i * 2 + w;
        const float4* row = reinterpret_cast<const float4*>(W1 + (size_t)c * 512);
        float acc = 0.0f;
#pragma unroll
        for (int q = 0; q < 4; q++) {
            float4 a = __ldg(&row[lane + 32 * q]);
            float4 g = __ldcg(reinterpret_cast<const float4*>(&g_geo[4 * (lane + 32 * q)]));
            acc += a.x * g.x + a.y * g.y + a.z * g.z + a.w * g.w;
        }
#pragma unroll
        for (int o = 16; o > 0; o >>= 1)
            acc += __shfl_xor_sync(0xffffffffu, acc, o);
        if (lane == 0) g_h1[c] = acc + __ldg(&b1[c]);
    }
    __threadfence();
    __syncthreads();
    if (t == 0) atomicAdd(&g_ctr2, 1u);
    if (i != 0) return;

    // ================== Phase 3: block 0 finishes the MLP ===================
    if (t == 0) { while (vpoll(&g_ctr2) < 128u) {} }
    __syncthreads();
    __threadfence();

    // GroupNorm1 (8 groups x 32 = warp per group) + ReLU
    {
        float x = __ldcg(&g_h1[t]);
        float s = x;
#pragma unroll
        for (int o = 16; o > 0; o >>= 1) s += __shfl_xor_sync(0xffffffffu, s, o);
        float mean = s * (1.0f / 32.0f);
        float ee = x - mean;
        float v = ee * ee;
#pragma unroll
        for (int o = 16; o > 0; o >>= 1) v += __shfl_xor_sync(0xffffffffu, v, o);
        v *= (1.0f / 32.0f);
        float xn = ee / sqrtf(v + 1e-5f) * __ldg(&gm1[t]) + __ldg(&bt1[t]);
        ha[t] = fmaxf(xn, 0.0f);
    }
    __syncthreads();

    // fc2: 256 -> 128, 8 warps x 16 channels
    {
        const float4* ha4 = reinterpret_cast<const float4*>(ha);
        float4 hv0 = ha4[lane], hv1 = ha4[lane + 32];
#pragma unroll 4
        for (int cc = 0; cc < 16; cc++) {
            int c = (w << 4) | cc;
            const float4* row = reinterpret_cast<const float4*>(W2 + (size_t)c * 256);
            float4 a0 = __ldg(&row[lane]);
            float4 a1 = __ldg(&row[lane + 32]);
            float acc = a0.x * hv0.x + a0.y * hv0.y + a0.z * hv0.z + a0.w * hv0.w
                      + a1.x * hv1.x + a1.y * hv1.y + a1.z * hv1.z + a1.w * hv1.w;
#pragma unroll
            for (int o = 16; o > 0; o >>= 1)
                acc += __shfl_xor_sync(0xffffffffu, acc, o);
            if (lane == 0) h2s[c] = acc + __ldg(&b2[c]);
        }
    }
    __syncthreads();

    // GroupNorm2 (8 groups x 16 = half-warp per group) + ReLU
    if (t < 128) {
        float x = h2s[t];
        float s = x;
#pragma unroll
        for (int o = 8; o > 0; o >>= 1) s += __shfl_xor_sync(0xffffffffu, s, o);
        float mean = s * (1.0f / 16.0f);
        float ee = x - mean;
        float v = ee * ee;
#pragma unroll
        for (int o = 8; o > 0; o >>= 1) v += __shfl_xor_sync(0xffffffffu, v, o);
        v *= (1.0f / 16.0f);
        float xn = ee / sqrtf(v + 1e-5f) * __ldg(&gm2[t]) + __ldg(&bt2[t]);
        h2a[t] = fmaxf(xn, 0.0f);
    }
    __syncthreads();

    // fc3: 128 -> 2
    if (w < 2) {
        const float4* row = reinterpret_cast<const float4*>(W3 + (size_t)w * 128);
        float4 a = __ldg(&row[lane]);
        float4 g = reinterpret_cast<const float4*>(h2a)[lane];
        float acc = a.x * g.x + a.y * g.y + a.z * g.z + a.w * g.w;
#pragma unroll
        for (int o = 16; o > 0; o >>= 1)
            acc += __shfl_xor_sync(0xffffffffu, acc, o);
        if (lane == 0) out[w] = acc + __ldg(&b3[w]);
    }

    // ---- reset state for next graph replay ----
    if (t < 128)      g_colkey_d[t] = 0ull;
    else              g_colkey_f[t - 128] = 0ull;
    if (t == 0) {
        g_ctr1 = 0u;
        g_ctr2 = 0u;
        *(volatile unsigned*)&g_flag = 0u;
    }
}

extern "C" void kernel_launch(void* const* d_in, const int* in_sizes, int n_in,
                              void* d_out, int out_size) {
    const float* pts   = (const float*)d_in[0];
    const float* reff  = (const float*)d_in[1];
    const float* srcf  = (const float*)d_in[2];
    const float* trans = (const float*)d_in[3];
    const float* W1  = (const float*)d_in[4];
    const float* b1  = (const float*)d_in[5];
    const float* g1  = (const float*)d_in[6];
    const float* bt1 = (const float*)d_in[7];
    const float* W2  = (const float*)d_in[8];
    const float* b2  = (const float*)d_in[9];
    const float* g2  = (const float*)d_in[10];
    const float* bt2 = (const float*)d_in[11];
    const float* W3  = (const float*)d_in[12];
    const float* b3  = (const float*)d_in[13];

    k_all<<<128, 256>>>(pts, trans, reff, srcf,
                        W1, b1, g1, bt1, W2, b2, g2, bt2, W3, b3,
                        (float*)d_out);
}

// round 5
// speedup vs baseline: 1.1825x; 1.1825x over previous
#include <cuda_runtime.h>
#include <math.h>

#define FD 256

// -------- device scratch (zero-initialized at module load) --------
__device__ float g_dist[128 * 128];
__device__ float g_feat[128 * 128];
__device__ float g_md[128], g_fs[128], g_mf[128], g_mdist[128];
__device__ unsigned long long g_colkey_d[128], g_colkey_f[128];
__device__ float g_h1[256];
__device__ float g_h2[128];
__device__ unsigned g_ctr1, g_ctr2, g_ctr3;

__device__ __forceinline__ unsigned f2o(float f) {
    unsigned u = __float_as_uint(f);
    return (u & 0x80000000u) ? ~u : (u | 0x80000000u);
}
__device__ __forceinline__ unsigned long long pk(float v, unsigned inv_idx) {
    return (((unsigned long long)f2o(v)) << 32) | (unsigned long long)inv_idx;
}
__device__ __forceinline__ unsigned vpoll(unsigned* p) {
    return *(volatile unsigned*)p;
}

__global__ void __launch_bounds__(256)
k_all(const float* __restrict__ pts, const float* __restrict__ trans,
      const float* __restrict__ ref_f, const float* __restrict__ src_f,
      const float* __restrict__ W1, const float* __restrict__ b1,
      const float* __restrict__ gm1, const float* __restrict__ bt1,
      const float* __restrict__ W2, const float* __restrict__ b2,
      const float* __restrict__ gm2, const float* __restrict__ bt2,
      const float* __restrict__ W3, const float* __restrict__ b3,
      float* __restrict__ out) {
    __shared__ float spx[256], spy[256], spz[256], ssq[256];
    __shared__ __align__(16) float sref[FD];
    __shared__ float sdrow[128], sfrow[128];
    __shared__ float sred[24], smax[8];
    __shared__ unsigned long long swd[4], swf[4];
    // prefetched weights
    __shared__ __align__(16) float4 sW1[256];   // rows 2i, 2i+1 of W1
    __shared__ __align__(16) float4 sW2[64];    // row i of W2
    __shared__ float sg1[256], sb1g[256];       // gm1, bt1
    __shared__ float sb_fc1[2], sb_fc2;
    // post-barrier work
    __shared__ float smd[256], sfs[256], smf[256], smdist[256];
    __shared__ __align__(16) unsigned long long sk1[256], sk2[256];
    __shared__ __align__(16) float sgeo[512];
    __shared__ __align__(16) float sha[256];
    // block-0 tail
    __shared__ float sh2[128];
    __shared__ __align__(16) float sh2a[128];

    const int t = threadIdx.x;
    const int i = blockIdx.x;
    const int w = t >> 5, lane = t & 31;

    // ============ prefetch post-barrier operands (overlaps phase 1) =========
    sW1[t] = __ldg(&reinterpret_cast<const float4*>(W1)[i * 256 + t]);
    if (t < 64)  sW2[t] = __ldg(&reinterpret_cast<const float4*>(W2)[i * 64 + t]);
    sg1[t]  = __ldg(&gm1[t]);
    sb1g[t] = __ldg(&bt1[t]);
    if (t < 2)       sb_fc1[t] = __ldg(&b1[2 * i + t]);
    else if (t == 2) sb_fc2    = __ldg(&b2[i]);

    // ===================== Phase 1: normalize + my row ======================
    sref[t] = __ldg(&ref_f[i * FD + t]);

    float tr0 = __ldg(&trans[0]), tr1 = __ldg(&trans[1]), tr2  = __ldg(&trans[2]),  tr3  = __ldg(&trans[3]);
    float tr4 = __ldg(&trans[4]), tr5 = __ldg(&trans[5]), tr6  = __ldg(&trans[6]),  tr7  = __ldg(&trans[7]);
    float tr8 = __ldg(&trans[8]), tr9 = __ldg(&trans[9]), tr10 = __ldg(&trans[10]), tr11 = __ldg(&trans[11]);

    float px = pts[3 * t + 0];
    float py = pts[3 * t + 1];
    float pz = pts[3 * t + 2];
    if (t >= 128) {
        float x = tr0 * px + tr1 * py + tr2  * pz + tr3;
        float y = tr4 * px + tr5 * py + tr6  * pz + tr7;
        float z = tr8 * px + tr9 * py + tr10 * pz + tr11;
        px = x; py = y; pz = z;
    }
    float lx = px, ly = py, lz = pz;
#pragma unroll
    for (int o = 16; o > 0; o >>= 1) {
        lx += __shfl_xor_sync(0xffffffffu, lx, o);
        ly += __shfl_xor_sync(0xffffffffu, ly, o);
        lz += __shfl_xor_sync(0xffffffffu, lz, o);
    }
    if (lane == 0) { sred[w] = lx; sred[8 + w] = ly; sred[16 + w] = lz; }
    __syncthreads();
    float cx = 0.f, cy = 0.f, cz = 0.f;
#pragma unroll
    for (int q = 0; q < 8; q++) { cx += sred[q]; cy += sred[8 + q]; cz += sred[16 + q]; }
    cx *= (1.0f / 256.0f); cy *= (1.0f / 256.0f); cz *= (1.0f / 256.0f);

    px -= cx; py -= cy; pz -= cz;
    float sq = px * px + py * py + pz * pz;
    float lm = sq;
#pragma unroll
    for (int o = 16; o > 0; o >>= 1)
        lm = fmaxf(lm, __shfl_xor_sync(0xffffffffu, lm, o));
    if (lane == 0) smax[w] = lm;
    __syncthreads();
    float m2 = smax[0];
#pragma unroll
    for (int q = 1; q < 8; q++) m2 = fmaxf(m2, smax[q]);
    float inv = 1.0f / sqrtf(m2);
    spx[t] = px * inv; spy[t] = py * inv; spz[t] = pz * inv;
    ssq[t] = sq * inv * inv;
    __syncthreads();

    // dist entry (i, j=t) for t<128
    float e = 0.f;
    if (t < 128) {
        float rx = spx[i], ry = spy[i], rz = spz[i];
        int sj = 128 + t;
        float d = ssq[i] + ssq[sj] - 2.0f * (rx * spx[sj] + ry * spy[sj] + rz * spz[sj]);
        d = fmaxf(d, 0.0f);
        e = expf(-d);
        g_dist[i * 128 + t] = e;
        sdrow[t] = e;
        atomicMax(&g_colkey_d[t], pk(e, 127u - (unsigned)i));
    }

    // feat row: 8 warps x 16 src rows, coalesced
    {
        const float4* sr4 = reinterpret_cast<const float4*>(sref);
        float4 r0 = sr4[lane];
        float4 r1 = sr4[lane + 32];
        int jb = w * 16;
#pragma unroll 4
        for (int jj = 0; jj < 16; jj++) {
            int j = jb + jj;
            const float4* s4 = reinterpret_cast<const float4*>(src_f + (size_t)j * FD);
            float4 a0 = __ldg(&s4[lane]);
            float4 a1 = __ldg(&s4[lane + 32]);
            float acc = a0.x * r0.x + a0.y * r0.y + a0.z * r0.z + a0.w * r0.w
                      + a1.x * r1.x + a1.y * r1.y + a1.z * r1.z + a1.w * r1.w;
#pragma unroll
            for (int o = 16; o > 0; o >>= 1)
                acc += __shfl_xor_sync(0xffffffffu, acc, o);
            if (lane == 0) sfrow[j] = acc;
        }
    }
    __syncthreads();
    if (t < 128) {
        float fv = sfrow[t];
        g_feat[i * 128 + t] = fv;
        atomicMax(&g_colkey_f[t], pk(fv, 127u - (unsigned)i));
        unsigned long long kd = pk(e,  127u - (unsigned)t);
        unsigned long long kf = pk(fv, 127u - (unsigned)t);
#pragma unroll
        for (int o = 16; o > 0; o >>= 1) {
            unsigned long long od = __shfl_xor_sync(0xffffffffu, kd, o);
            unsigned long long of = __shfl_xor_sync(0xffffffffu, kf, o);
            if (od > kd) kd = od;
            if (of > kf) kf = of;
        }
        if (lane == 0) { swd[w] = kd; swf[w] = kf; }
    }
    __syncthreads();
    if (t == 0) {
        unsigned long long bd = swd[0], bf = swf[0];
#pragma unroll
        for (int q = 1; q < 4; q++) {
            if (swd[q] > bd) bd = swd[q];
            if (swf[q] > bf) bf = swf[q];
        }
        int jd = 127 - (int)(bd & 0xFFFFFFFFull);
        int jf = 127 - (int)(bf & 0xFFFFFFFFull);
        g_md[i]    = sdrow[jd];
        g_fs[i]    = sfrow[jd];
        g_mf[i]    = sfrow[jf];
        g_mdist[i] = sdrow[jf];
    }

    // ===================== grid barrier #1 =====================
    __threadfence();
    __syncthreads();
    if (t == 0) {
        atomicAdd(&g_ctr1, 1u);
        while (vpoll(&g_ctr1) < 128u) {}
        __threadfence();
    }
    __syncthreads();

    // ============== Phase 2 (ALL blocks): assemble + rank + fc1 =============
    if (t < 128) {
        smd[t]    = __ldcg(&g_md[t]);
        sfs[t]    = __ldcg(&g_fs[t]);
        smf[t]    = __ldcg(&g_mf[t]);
        smdist[t] = __ldcg(&g_mdist[t]);
    } else {
        int c = t - 128;
        unsigned long long kd = __ldcg(&g_colkey_d[c]);
        unsigned long long kf = __ldcg(&g_colkey_f[c]);
        int id = 127 - (int)(kd & 0xFFFFFFFFull);
        int jf = 127 - (int)(kf & 0xFFFFFFFFull);
        smd[t]    = __ldcg(&g_dist[id * 128 + c]);
        sfs[t]    = __ldcg(&g_feat[id * 128 + c]);
        smf[t]    = __ldcg(&g_feat[jf * 128 + c]);
        smdist[t] = __ldcg(&g_dist[jf * 128 + c]);
    }
    __syncthreads();

    unsigned long long k1 = pk(smd[t], 255u - (unsigned)t);
    unsigned long long k2 = pk(smf[t], 255u - (unsigned)t);
    sk1[t] = k1; sk2[t] = k2;
    __syncthreads();
    {
        int r1 = 0, r2 = 0;
        const ulonglong2* p1 = reinterpret_cast<const ulonglong2*>(sk1);
        const ulonglong2* p2 = reinterpret_cast<const ulonglong2*>(sk2);
#pragma unroll 8
        for (int j = 0; j < 128; j++) {
            ulonglong2 a = p1[j];
            ulonglong2 b = p2[j];
            r1 += (a.x > k1) ? 1 : 0;
            r1 += (a.y > k1) ? 1 : 0;
            r2 += (b.x > k2) ? 1 : 0;
            r2 += (b.y > k2) ? 1 : 0;
        }
        sgeo[r1]       = smd[t] * sfs[t];
        sgeo[256 + r2] = smdist[t] * smf[t];
    }
    __syncthreads();

    // fc1: this block's 2 channels, weights already in shared
    if (w < 2) {
        const float4* geo4 = reinterpret_cast<const float4*>(sgeo);
        float acc = 0.0f;
#pragma unroll
        for (int q = 0; q < 4; q++) {
            float4 a = sW1[w * 128 + lane + 32 * q];
            float4 g = geo4[lane + 32 * q];
            acc += a.x * g.x + a.y * g.y + a.z * g.z + a.w * g.w;
        }
#pragma unroll
        for (int o = 16; o > 0; o >>= 1)
            acc += __shfl_xor_sync(0xffffffffu, acc, o);
        if (lane == 0) g_h1[2 * i + w] = acc + sb_fc1[w];
    }

    // ===================== grid barrier #2 =====================
    __threadfence();
    __syncthreads();
    if (t == 0) {
        atomicAdd(&g_ctr2, 1u);
        while (vpoll(&g_ctr2) < 128u) {}
        __threadfence();
    }
    __syncthreads();

    // ============== Phase 3 (ALL blocks): GN1 + 1 fc2 channel ===============
    {
        float x = __ldcg(&g_h1[t]);
        float s = x;
#pragma unroll
        for (int o = 16; o > 0; o >>= 1) s += __shfl_xor_sync(0xffffffffu, s, o);
        float mean = s * (1.0f / 32.0f);
        float ee = x - mean;
        float v = ee * ee;
#pragma unroll
        for (int o = 16; o > 0; o >>= 1) v += __shfl_xor_sync(0xffffffffu, v, o);
        v *= (1.0f / 32.0f);
        float xn = ee / sqrtf(v + 1e-5f) * sg1[t] + sb1g[t];
        sha[t] = fmaxf(xn, 0.0f);
    }
    __syncthreads();

    if (w == 0) {
        const float4* ha4 = reinterpret_cast<const float4*>(sha);
        float4 a0 = sW2[lane];
        float4 a1 = sW2[lane + 32];
        float4 h0 = ha4[lane];
        float4 h1v = ha4[lane + 32];
        float acc = a0.x * h0.x + a0.y * h0.y + a0.z * h0.z + a0.w * h0.w
                  + a1.x * h1v.x + a1.y * h1v.y + a1.z * h1v.z + a1.w * h1v.w;
#pragma unroll
        for (int o = 16; o > 0; o >>= 1)
            acc += __shfl_xor_sync(0xffffffffu, acc, o);
        if (lane == 0) g_h2[i] = acc + sb_fc2;
    }

    // distributed state reset (colkeys consumed by every block before B2)
    if (t == 0) { g_colkey_d[i] = 0ull; g_colkey_f[i] = 0ull; }

    // ===================== grid barrier #3 =====================
    __threadfence();
    __syncthreads();
    if (t == 0) atomicAdd(&g_ctr3, 1u);
    if (i != 0) return;

    if (t == 0) {
        while (vpoll(&g_ctr3) < 128u) {}
        __threadfence();
    }
    __syncthreads();

    // ================= Phase 4 (block 0): GN2 + fc3 -> out ==================
    if (t < 128) sh2[t] = __ldcg(&g_h2[t]);
    __syncthreads();
    if (t < 128) {
        float x = sh2[t];
        float s = x;
#pragma unroll
        for (int o = 8; o > 0; o >>= 1) s += __shfl_xor_sync(0xffffffffu, s, o);
        float mean = s * (1.0f / 16.0f);
        float ee = x - mean;
        float v = ee * ee;
#pragma unroll
        for (int o = 8; o > 0; o >>= 1) v += __shfl_xor_sync(0xffffffffu, v, o);
        v *= (1.0f / 16.0f);
        float xn = ee / sqrtf(v + 1e-5f) * __ldg(&gm2[t]) + __ldg(&bt2[t]);
        sh2a[t] = fmaxf(xn, 0.0f);
    }
    __syncthreads();

    if (w < 2) {
        const float4* row = reinterpret_cast<const float4*>(W3 + (size_t)w * 128);
        float4 a = __ldg(&row[lane]);
        float4 g = reinterpret_cast<const float4*>(sh2a)[lane];
        float acc = a.x * g.x + a.y * g.y + a.z * g.z + a.w * g.w;
#pragma unroll
        for (int o = 16; o > 0; o >>= 1)
            acc += __shfl_xor_sync(0xffffffffu, acc, o);
        if (lane == 0) out[w] = acc + __ldg(&b3[w]);
    }

    // reset barrier counters for next graph replay
    if (t == 0) { g_ctr1 = 0u; g_ctr2 = 0u; g_ctr3 = 0u; }
}

extern "C" void kernel_launch(void* const* d_in, const int* in_sizes, int n_in,
                              void* d_out, int out_size) {
    const float* pts   = (const float*)d_in[0];
    const float* reff  = (const float*)d_in[1];
    const float* srcf  = (const float*)d_in[2];
    const float* trans = (const float*)d_in[3];
    const float* W1  = (const float*)d_in[4];
    const float* b1  = (const float*)d_in[5];
    const float* g1  = (const float*)d_in[6];
    const float* bt1 = (const float*)d_in[7];
    const float* W2  = (const float*)d_in[8];
    const float* b2  = (const float*)d_in[9];
    const float* g2  = (const float*)d_in[10];
    const float* bt2 = (const float*)d_in[11];
    const float* W3  = (const float*)d_in[12];
    const float* b3  = (const float*)d_in[13];

    k_all<<<128, 256>>>(pts, trans, reff, srcf,
                        W1, b1, g1, bt1, W2, b2, g2, bt2, W3, b3,
                        (float*)d_out);
}

// round 6
// speedup vs baseline: 1.4848x; 1.2557x over previous
#include <cuda_runtime.h>
#include <math.h>

#define FD 256

// -------- device scratch (zero-initialized at module load) --------
__device__ float g_dist[128 * 128];
__device__ float g_feat[128 * 128];
__device__ float g_md[128], g_fs[128], g_mf[128], g_mdist[128];
__device__ unsigned long long g_colkey_d[128], g_colkey_f[128];
__device__ float g_h1[256];
__device__ float g_h2[128];
__device__ unsigned g_ctr1, g_ctr2, g_ctr3;

__device__ __forceinline__ unsigned f2o(float f) {
    unsigned u = __float_as_uint(f);
    return (u & 0x80000000u) ? ~u : (u | 0x80000000u);
}
__device__ __forceinline__ unsigned long long pk(float v, unsigned inv_idx) {
    return (((unsigned long long)f2o(v)) << 32) | (unsigned long long)inv_idx;
}
// release arrival on a global counter (no L1 flush, unlike __threadfence)
__device__ __forceinline__ void bar_arrive(unsigned* ctr) {
    asm volatile("red.release.gpu.add.u32 [%0], 1;" :: "l"(ctr) : "memory");
}
__device__ __forceinline__ void bar_spin(unsigned* ctr, unsigned target) {
    unsigned v;
    do {
        asm volatile("ld.acquire.gpu.u32 %0, [%1];" : "=r"(v) : "l"(ctr) : "memory");
    } while (v < target);
}

__global__ void __launch_bounds__(512)
k_all(const float* __restrict__ pts, const float* __restrict__ trans,
      const float* __restrict__ ref_f, const float* __restrict__ src_f,
      const float* __restrict__ W1, const float* __restrict__ b1,
      const float* __restrict__ gm1, const float* __restrict__ bt1,
      const float* __restrict__ W2, const float* __restrict__ b2,
      const float* __restrict__ gm2, const float* __restrict__ bt2,
      const float* __restrict__ W3, const float* __restrict__ b3,
      float* __restrict__ out) {
    __shared__ float spx[256], spy[256], spz[256], ssq[256];
    __shared__ __align__(16) float sref[FD];
    __shared__ float sdrow[128], sfrow[128];
    __shared__ float sred[24], smax[8];
    __shared__ unsigned long long swd[4], swf[4];
    // prefetched weights
    __shared__ __align__(16) float4 sW1[256];   // W1 rows 2i, 2i+1
    __shared__ __align__(16) float4 sW2[64];    // W2 row i
    __shared__ float sg1[256], sb1g[256];
    __shared__ float sb_fc1[2], sb_fc2;
    // block-0 tail params
    __shared__ float sg2[128], sbt2[128], sb3[2];
    __shared__ __align__(16) float4 sW3[64];
    // post-barrier work
    __shared__ float smd[256], sfs[256], smf[256], smdist[256];
    __shared__ __align__(16) unsigned long long sk1[256], sk2[256];
    __shared__ __align__(16) float sgeo[512];
    __shared__ __align__(16) float sha[256];
    __shared__ float sh2[128];
    __shared__ __align__(16) float sh2a[128];

    const int t = threadIdx.x;
    const int i = blockIdx.x;
    const int w = t >> 5, lane = t & 31;

    // ============ prefetch post-barrier operands (overlaps phase 1) =========
    if (t < 256) {
        sW1[t]  = __ldg(&reinterpret_cast<const float4*>(W1)[i * 256 + t]);
        sg1[t]  = __ldg(&gm1[t]);
        sb1g[t] = __ldg(&bt1[t]);
        sref[t] = __ldg(&ref_f[i * FD + t]);
    } else {
        int q = t - 256;
        if (q < 64) sW2[q] = __ldg(&reinterpret_cast<const float4*>(W2)[i * 64 + q]);
        else if (q == 64) {
            sb_fc1[0] = __ldg(&b1[2 * i]);
            sb_fc1[1] = __ldg(&b1[2 * i + 1]);
            sb_fc2    = __ldg(&b2[i]);
        }
    }
    if (i == 0) {
        if (t >= 320 && t < 448) {
            int q = t - 320;
            sg2[q]  = __ldg(&gm2[q]);
            sbt2[q] = __ldg(&bt2[q]);
        } else if (t >= 448 && t < 512) {
            sW3[t - 448] = __ldg(&reinterpret_cast<const float4*>(W3)[t - 448]);
            if (t < 450) sb3[t - 448] = __ldg(&b3[t - 448]);
        }
    }

    // ===================== Phase 1: normalize + my row ======================
    float tr0 = __ldg(&trans[0]), tr1 = __ldg(&trans[1]), tr2  = __ldg(&trans[2]),  tr3  = __ldg(&trans[3]);
    float tr4 = __ldg(&trans[4]), tr5 = __ldg(&trans[5]), tr6  = __ldg(&trans[6]),  tr7  = __ldg(&trans[7]);
    float tr8 = __ldg(&trans[8]), tr9 = __ldg(&trans[9]), tr10 = __ldg(&trans[10]), tr11 = __ldg(&trans[11]);

    float px = 0.f, py = 0.f, pz = 0.f;
    if (t < 256) {
        px = pts[3 * t + 0];
        py = pts[3 * t + 1];
        pz = pts[3 * t + 2];
        if (t >= 128) {
            float x = tr0 * px + tr1 * py + tr2  * pz + tr3;
            float y = tr4 * px + tr5 * py + tr6  * pz + tr7;
            float z = tr8 * px + tr9 * py + tr10 * pz + tr11;
            px = x; py = y; pz = z;
        }
    }
    float lx = px, ly = py, lz = pz;
#pragma unroll
    for (int o = 16; o > 0; o >>= 1) {
        lx += __shfl_xor_sync(0xffffffffu, lx, o);
        ly += __shfl_xor_sync(0xffffffffu, ly, o);
        lz += __shfl_xor_sync(0xffffffffu, lz, o);
    }
    if (w < 8 && lane == 0) { sred[w] = lx; sred[8 + w] = ly; sred[16 + w] = lz; }
    __syncthreads();
    float cx = 0.f, cy = 0.f, cz = 0.f;
#pragma unroll
    for (int q = 0; q < 8; q++) { cx += sred[q]; cy += sred[8 + q]; cz += sred[16 + q]; }
    cx *= (1.0f / 256.0f); cy *= (1.0f / 256.0f); cz *= (1.0f / 256.0f);

    float sq = 0.f;
    if (t < 256) {
        px -= cx; py -= cy; pz -= cz;
        sq = px * px + py * py + pz * pz;
    }
    float lm = sq;
#pragma unroll
    for (int o = 16; o > 0; o >>= 1)
        lm = fmaxf(lm, __shfl_xor_sync(0xffffffffu, lm, o));
    if (w < 8 && lane == 0) smax[w] = lm;
    __syncthreads();
    float m2 = smax[0];
#pragma unroll
    for (int q = 1; q < 8; q++) m2 = fmaxf(m2, smax[q]);
    float inv = 1.0f / sqrtf(m2);
    if (t < 256) {
        spx[t] = px * inv; spy[t] = py * inv; spz[t] = pz * inv;
        ssq[t] = sq * inv * inv;
    }
    __syncthreads();

    // dist entry (i, j=t) for t<128
    float e = 0.f;
    if (t < 128) {
        float rx = spx[i], ry = spy[i], rz = spz[i];
        int sj = 128 + t;
        float d = ssq[i] + ssq[sj] - 2.0f * (rx * spx[sj] + ry * spy[sj] + rz * spz[sj]);
        d = fmaxf(d, 0.0f);
        e = expf(-d);
        g_dist[i * 128 + t] = e;
        sdrow[t] = e;
        atomicMax(&g_colkey_d[t], pk(e, 127u - (unsigned)i));
    }

    // feat row: 16 warps x 8 src rows, coalesced
    {
        const float4* sr4 = reinterpret_cast<const float4*>(sref);
        float4 r0 = sr4[lane];
        float4 r1 = sr4[lane + 32];
        int jb = w * 8;
#pragma unroll
        for (int jj = 0; jj < 8; jj++) {
            int j = jb + jj;
            const float4* s4 = reinterpret_cast<const float4*>(src_f + (size_t)j * FD);
            float4 a0 = __ldg(&s4[lane]);
            float4 a1 = __ldg(&s4[lane + 32]);
            float acc = a0.x * r0.x + a0.y * r0.y + a0.z * r0.z + a0.w * r0.w
                      + a1.x * r1.x + a1.y * r1.y + a1.z * r1.z + a1.w * r1.w;
#pragma unroll
            for (int o = 16; o > 0; o >>= 1)
                acc += __shfl_xor_sync(0xffffffffu, acc, o);
            if (lane == 0) sfrow[j] = acc;
        }
    }
    __syncthreads();
    if (t < 128) {
        float fv = sfrow[t];
        g_feat[i * 128 + t] = fv;
        atomicMax(&g_colkey_f[t], pk(fv, 127u - (unsigned)i));
        unsigned long long kd = pk(e,  127u - (unsigned)t);
        unsigned long long kf = pk(fv, 127u - (unsigned)t);
#pragma unroll
        for (int o = 16; o > 0; o >>= 1) {
            unsigned long long od = __shfl_xor_sync(0xffffffffu, kd, o);
            unsigned long long of = __shfl_xor_sync(0xffffffffu, kf, o);
            if (od > kd) kd = od;
            if (of > kf) kf = of;
        }
        if (lane == 0) { swd[w] = kd; swf[w] = kf; }
    }
    __syncthreads();

    // ===================== grid barrier #1 =====================
    if (t == 0) {
        unsigned long long bd = swd[0], bf = swf[0];
#pragma unroll
        for (int q = 1; q < 4; q++) {
            if (swd[q] > bd) bd = swd[q];
            if (swf[q] > bf) bf = swf[q];
        }
        int jd = 127 - (int)(bd & 0xFFFFFFFFull);
        int jf = 127 - (int)(bf & 0xFFFFFFFFull);
        g_md[i]    = sdrow[jd];
        g_fs[i]    = sfrow[jd];
        g_mf[i]    = sfrow[jf];
        g_mdist[i] = sdrow[jf];
        bar_arrive(&g_ctr1);
        bar_spin(&g_ctr1, 128u);
    }
    __syncthreads();

    // ============== Phase 2 (ALL blocks): assemble + rank + fc1 =============
    if (t < 128) {
        smd[t]    = __ldcg(&g_md[t]);
        sfs[t]    = __ldcg(&g_fs[t]);
        smf[t]    = __ldcg(&g_mf[t]);
        smdist[t] = __ldcg(&g_mdist[t]);
    } else if (t < 256) {
        int c = t - 128;
        unsigned long long kd = __ldcg(&g_colkey_d[c]);
        unsigned long long kf = __ldcg(&g_colkey_f[c]);
        int id = 127 - (int)(kd & 0xFFFFFFFFull);
        int jf = 127 - (int)(kf & 0xFFFFFFFFull);
        smd[t]    = __ldcg(&g_dist[id * 128 + c]);
        sfs[t]    = __ldcg(&g_feat[id * 128 + c]);
        smf[t]    = __ldcg(&g_feat[jf * 128 + c]);
        smdist[t] = __ldcg(&g_dist[jf * 128 + c]);
    }
    __syncthreads();

    // keys: threads 0-255 own sort1 entry t; threads 256-511 own sort2 entry t-256
    unsigned long long mykey;
    if (t < 256) { mykey = pk(smd[t], 255u - (unsigned)t); sk1[t] = mykey; }
    else         { int c = t - 256; mykey = pk(smf[c], 255u - (unsigned)c); sk2[c] = mykey; }
    __syncthreads();
    {
        const ulonglong2* p = reinterpret_cast<const ulonglong2*>((t < 256) ? sk1 : sk2);
        int r = 0;
#pragma unroll 8
        for (int j = 0; j < 128; j++) {
            ulonglong2 a = p[j];
            r += (a.x > mykey) ? 1 : 0;
            r += (a.y > mykey) ? 1 : 0;
        }
        if (t < 256) sgeo[r] = smd[t] * sfs[t];
        else         { int c = t - 256; sgeo[256 + r] = smdist[c] * smf[c]; }
    }
    __syncthreads();

    // fc1: this block's 2 channels, weights in shared
    if (w < 2) {
        const float4* geo4 = reinterpret_cast<const float4*>(sgeo);
        float acc = 0.0f;
#pragma unroll
        for (int q = 0; q < 4; q++) {
            float4 a = sW1[w * 128 + lane + 32 * q];
            float4 g = geo4[lane + 32 * q];
            acc += a.x * g.x + a.y * g.y + a.z * g.z + a.w * g.w;
        }
#pragma unroll
        for (int o = 16; o > 0; o >>= 1)
            acc += __shfl_xor_sync(0xffffffffu, acc, o);
        if (lane == 0) g_h1[2 * i + w] = acc + sb_fc1[w];
    }

    // ===================== grid barrier #2 =====================
    __syncthreads();
    if (t == 0) {
        bar_arrive(&g_ctr2);
        bar_spin(&g_ctr2, 128u);
    }
    __syncthreads();

    // ============== Phase 3 (ALL blocks): GN1 + 1 fc2 channel ===============
    if (t < 256) {
        float x = __ldcg(&g_h1[t]);
        float s = x;
#pragma unroll
        for (int o = 16; o > 0; o >>= 1) s += __shfl_xor_sync(0xffffffffu, s, o);
        float mean = s * (1.0f / 32.0f);
        float ee = x - mean;
        float v = ee * ee;
#pragma unroll
        for (int o = 16; o > 0; o >>= 1) v += __shfl_xor_sync(0xffffffffu, v, o);
        v *= (1.0f / 32.0f);
        float xn = ee / sqrtf(v + 1e-5f) * sg1[t] + sb1g[t];
        sha[t] = fmaxf(xn, 0.0f);
    }
    __syncthreads();

    if (w == 0) {
        const float4* ha4 = reinterpret_cast<const float4*>(sha);
        float4 a0 = sW2[lane];
        float4 a1 = sW2[lane + 32];
        float4 h0 = ha4[lane];
        float4 h1v = ha4[lane + 32];
        float acc = a0.x * h0.x + a0.y * h0.y + a0.z * h0.z + a0.w * h0.w
                  + a1.x * h1v.x + a1.y * h1v.y + a1.z * h1v.z + a1.w * h1v.w;
#pragma unroll
        for (int o = 16; o > 0; o >>= 1)
            acc += __shfl_xor_sync(0xffffffffu, acc, o);
        if (lane == 0) g_h2[i] = acc + sb_fc2;
    }
    // distributed state reset (colkeys consumed by every block in phase 2)
    if (t == 1) { g_colkey_d[i] = 0ull; g_colkey_f[i] = 0ull; }

    // ===================== grid barrier #3 (block 0 waits) =====================
    __syncthreads();
    if (t == 0) bar_arrive(&g_ctr3);
    if (i != 0) return;
    if (t == 0) bar_spin(&g_ctr3, 128u);
    __syncthreads();

    // ================= Phase 4 (block 0): GN2 + fc3 -> out ==================
    if (t < 128) sh2[t] = __ldcg(&g_h2[t]);
    __syncthreads();
    if (t < 128) {
        float x = sh2[t];
        float s = x;
#pragma unroll
        for (int o = 8; o > 0; o >>= 1) s += __shfl_xor_sync(0xffffffffu, s, o);
        float mean = s * (1.0f / 16.0f);
        float ee = x - mean;
        float v = ee * ee;
#pragma unroll
        for (int o = 8; o > 0; o >>= 1) v += __shfl_xor_sync(0xffffffffu, v, o);
        v *= (1.0f / 16.0f);
        float xn = ee / sqrtf(v + 1e-5f) * sg2[t] + sbt2[t];
        sh2a[t] = fmaxf(xn, 0.0f);
    }
    __syncthreads();

    if (w < 2) {
        float4 a = sW3[w * 32 + lane];
        float4 g = reinterpret_cast<const float4*>(sh2a)[lane];
        float acc = a.x * g.x + a.y * g.y + a.z * g.z + a.w * g.w;
#pragma unroll
        for (int o = 16; o > 0; o >>= 1)
            acc += __shfl_xor_sync(0xffffffffu, acc, o);
        if (lane == 0) out[w] = acc + sb3[w];
    }

    // reset barrier counters for next graph replay
    if (t == 0) { g_ctr1 = 0u; g_ctr2 = 0u; g_ctr3 = 0u; }
}

extern "C" void kernel_launch(void* const* d_in, const int* in_sizes, int n_in,
                              void* d_out, int out_size) {
    const float* pts   = (const float*)d_in[0];
    const float* reff  = (const float*)d_in[1];
    const float* srcf  = (const float*)d_in[2];
    const float* trans = (const float*)d_in[3];
    const float* W1  = (const float*)d_in[4];
    const float* b1  = (const float*)d_in[5];
    const float* g1  = (const float*)d_in[6];
    const float* bt1 = (const float*)d_in[7];
    const float* W2  = (const float*)d_in[8];
    const float* b2  = (const float*)d_in[9];
    const float* g2  = (const float*)d_in[10];
    const float* bt2 = (const float*)d_in[11];
    const float* W3  = (const float*)d_in[12];
    const float* b3  = (const float*)d_in[13];

    k_all<<<128, 512>>>(pts, trans, reff, srcf,
                        W1, b1, g1, bt1, W2, b2, g2, bt2, W3, b3,
                        (float*)d_out);
}

// round 7
// speedup vs baseline: 1.6897x; 1.1379x over previous
#include <cuda_runtime.h>
#include <math.h>

#define FD 256

// -------- device scratch (zero-initialized at module load) --------
__device__ float g_dist[128 * 128];
__device__ float g_feat[128 * 128];
__device__ float g_md[128], g_fs[128], g_mf[128], g_mdist[128];
__device__ unsigned long long g_colkey_d[128], g_colkey_f[128];
__device__ __align__(16) float g_geo[512];
__device__ float g_h1[256];
__device__ unsigned g_ctr1, g_ctr2, g_ctr3;

__device__ __forceinline__ unsigned f2o(float f) {
    unsigned u = __float_as_uint(f);
    return (u & 0x80000000u) ? ~u : (u | 0x80000000u);
}
__device__ __forceinline__ unsigned long long pk(float v, unsigned inv_idx) {
    return (((unsigned long long)f2o(v)) << 32) | (unsigned long long)inv_idx;
}
// release arrival / acquire spin (no L1 flush)
__device__ __forceinline__ void bar_arrive(unsigned* ctr) {
    asm volatile("red.release.gpu.add.u32 [%0], 1;" :: "l"(ctr) : "memory");
}
__device__ __forceinline__ void bar_spin(unsigned* ctr, unsigned target) {
    unsigned v;
    do {
        asm volatile("ld.acquire.gpu.u32 %0, [%1];" : "=r"(v) : "l"(ctr) : "memory");
    } while (v < target);
}

__global__ void __launch_bounds__(512)
k_all(const float* __restrict__ pts, const float* __restrict__ trans,
      const float* __restrict__ ref_f, const float* __restrict__ src_f,
      const float* __restrict__ W1, const float* __restrict__ b1,
      const float* __restrict__ gm1, const float* __restrict__ bt1,
      const float* __restrict__ W2, const float* __restrict__ b2,
      const float* __restrict__ gm2, const float* __restrict__ bt2,
      const float* __restrict__ W3, const float* __restrict__ b3,
      float* __restrict__ out) {
    __shared__ float spx[256], spy[256], spz[256], ssq[256];
    __shared__ __align__(16) float sref[FD];
    __shared__ float sdrow[128], sfrow[128];
    __shared__ float sred[24], smax[8];
    // prefetched per-block weights
    __shared__ __align__(16) float4 sW1[256];   // W1 rows 2i, 2i+1
    __shared__ float sb_fc1[2];
    // block-0 tail params
    __shared__ float sg1[256], sb1g[256];
    __shared__ float sg2[128], sbt2[128], sb2[128], sb3[2];
    __shared__ __align__(16) float4 sW3[64];
    // post-barrier work
    __shared__ float smd[256], sfs[256], smf[256], smdist[256];
    __shared__ __align__(16) unsigned long long sk1[256], sk2[256];
    __shared__ __align__(16) float sha[256];
    __shared__ float sh2[128];
    __shared__ __align__(16) float sh2a[128];

    const int t = threadIdx.x;
    const int i = blockIdx.x;
    const int w = t >> 5, lane = t & 31;

    // ============ prefetch (overlaps phase 1) ============
    if (t < 256) {
        sW1[t]  = __ldg(&reinterpret_cast<const float4*>(W1)[i * 256 + t]);
        sref[t] = __ldg(&ref_f[i * FD + t]);
    }
    if (t == 256) {
        sb_fc1[0] = __ldg(&b1[2 * i]);
        sb_fc1[1] = __ldg(&b1[2 * i + 1]);
    }
    if (i == 0) {
        if (t < 256) {
            sg1[t]  = __ldg(&gm1[t]);
            sb1g[t] = __ldg(&bt1[t]);
        } else if (t < 384) {
            int q = t - 256;
            sg2[q]  = __ldg(&gm2[q]);
            sbt2[q] = __ldg(&bt2[q]);
            sb2[q]  = __ldg(&b2[q]);
        } else if (t < 448) {
            sW3[t - 384] = __ldg(&reinterpret_cast<const float4*>(W3)[t - 384]);
        } else if (t < 450) {
            sb3[t - 448] = __ldg(&b3[t - 448]);
        }
    }

    // ===================== Phase 1: normalize + my row ======================
    float tr0 = __ldg(&trans[0]), tr1 = __ldg(&trans[1]), tr2  = __ldg(&trans[2]),  tr3  = __ldg(&trans[3]);
    float tr4 = __ldg(&trans[4]), tr5 = __ldg(&trans[5]), tr6  = __ldg(&trans[6]),  tr7  = __ldg(&trans[7]);
    float tr8 = __ldg(&trans[8]), tr9 = __ldg(&trans[9]), tr10 = __ldg(&trans[10]), tr11 = __ldg(&trans[11]);

    float px = 0.f, py = 0.f, pz = 0.f;
    if (t < 256) {
        px = pts[3 * t + 0];
        py = pts[3 * t + 1];
        pz = pts[3 * t + 2];
        if (t >= 128) {
            float x = tr0 * px + tr1 * py + tr2  * pz + tr3;
            float y = tr4 * px + tr5 * py + tr6  * pz + tr7;
            float z = tr8 * px + tr9 * py + tr10 * pz + tr11;
            px = x; py = y; pz = z;
        }
    }
    float lx = px, ly = py, lz = pz;
#pragma unroll
    for (int o = 16; o > 0; o >>= 1) {
        lx += __shfl_xor_sync(0xffffffffu, lx, o);
        ly += __shfl_xor_sync(0xffffffffu, ly, o);
        lz += __shfl_xor_sync(0xffffffffu, lz, o);
    }
    if (w < 8 && lane == 0) { sred[w] = lx; sred[8 + w] = ly; sred[16 + w] = lz; }
    __syncthreads();
    float cx = 0.f, cy = 0.f, cz = 0.f;
#pragma unroll
    for (int q = 0; q < 8; q++) { cx += sred[q]; cy += sred[8 + q]; cz += sred[16 + q]; }
    cx *= (1.0f / 256.0f); cy *= (1.0f / 256.0f); cz *= (1.0f / 256.0f);

    float sq = 0.f;
    if (t < 256) {
        px -= cx; py -= cy; pz -= cz;
        sq = px * px + py * py + pz * pz;
    }
    float lm = sq;
#pragma unroll
    for (int o = 16; o > 0; o >>= 1)
        lm = fmaxf(lm, __shfl_xor_sync(0xffffffffu, lm, o));
    if (w < 8 && lane == 0) smax[w] = lm;
    __syncthreads();
    float m2 = smax[0];
#pragma unroll
    for (int q = 1; q < 8; q++) m2 = fmaxf(m2, smax[q]);
    float inv = 1.0f / sqrtf(m2);
    if (t < 256) {
        spx[t] = px * inv; spy[t] = py * inv; spz[t] = pz * inv;
        ssq[t] = sq * inv * inv;
    }
    __syncthreads();

    // dist entry (i, j=t) for t<128
    if (t < 128) {
        float rx = spx[i], ry = spy[i], rz = spz[i];
        int sj = 128 + t;
        float d = ssq[i] + ssq[sj] - 2.0f * (rx * spx[sj] + ry * spy[sj] + rz * spz[sj]);
        d = fmaxf(d, 0.0f);
        float e = expf(-d);
        g_dist[i * 128 + t] = e;
        sdrow[t] = e;
        atomicMax(&g_colkey_d[t], pk(e, 127u - (unsigned)i));
    }

    // feat row: 16 warps x 8 src rows, coalesced
    {
        const float4* sr4 = reinterpret_cast<const float4*>(sref);
        float4 r0 = sr4[lane];
        float4 r1 = sr4[lane + 32];
        int jb = w * 8;
#pragma unroll
        for (int jj = 0; jj < 8; jj++) {
            int j = jb + jj;
            const float4* s4 = reinterpret_cast<const float4*>(src_f + (size_t)j * FD);
            float4 a0 = __ldg(&s4[lane]);
            float4 a1 = __ldg(&s4[lane + 32]);
            float acc = a0.x * r0.x + a0.y * r0.y + a0.z * r0.z + a0.w * r0.w
                      + a1.x * r1.x + a1.y * r1.y + a1.z * r1.z + a1.w * r1.w;
#pragma unroll
            for (int o = 16; o > 0; o >>= 1)
                acc += __shfl_xor_sync(0xffffffffu, acc, o);
            if (lane == 0) sfrow[j] = acc;
        }
    }
    __syncthreads();
    if (t < 128) {
        float fv = sfrow[t];
        g_feat[i * 128 + t] = fv;
        atomicMax(&g_colkey_f[t], pk(fv, 127u - (unsigned)i));
    }
    // row argmaxes: single warp-0 scan of sdrow/sfrow (written before the sync)
    if (w == 0) {
        unsigned long long kd = 0ull, kf = 0ull;
#pragma unroll
        for (int q = 0; q < 4; q++) {
            int idx = lane + 32 * q;
            unsigned long long cd = pk(sdrow[idx], 127u - (unsigned)idx);
            unsigned long long cf = pk(sfrow[idx], 127u - (unsigned)idx);
            if (cd > kd) kd = cd;
            if (cf > kf) kf = cf;
        }
#pragma unroll
        for (int o = 16; o > 0; o >>= 1) {
            unsigned long long od = __shfl_xor_sync(0xffffffffu, kd, o);
            unsigned long long of = __shfl_xor_sync(0xffffffffu, kf, o);
            if (od > kd) kd = od;
            if (of > kf) kf = of;
        }
        if (lane == 0) {
            int jd = 127 - (int)(kd & 0xFFFFFFFFull);
            int jf = 127 - (int)(kf & 0xFFFFFFFFull);
            g_md[i]    = sdrow[jd];
            g_fs[i]    = sfrow[jd];
            g_mf[i]    = sfrow[jf];
            g_mdist[i] = sdrow[jf];
        }
    }

    // ===================== grid barrier #1 =====================
    __syncthreads();
    if (t == 0) {
        bar_arrive(&g_ctr1);
        bar_spin(&g_ctr1, 128u);
    }
    __syncthreads();

    // ====== Phase 2: assemble + keys; each block ranks its 4 elements =======
    if (t < 128) {
        smd[t]    = __ldcg(&g_md[t]);
        sfs[t]    = __ldcg(&g_fs[t]);
        smf[t]    = __ldcg(&g_mf[t]);
        smdist[t] = __ldcg(&g_mdist[t]);
    } else if (t < 256) {
        int c = t - 128;
        unsigned long long kd = __ldcg(&g_colkey_d[c]);
        unsigned long long kf = __ldcg(&g_colkey_f[c]);
        int id = 127 - (int)(kd & 0xFFFFFFFFull);
        int jf = 127 - (int)(kf & 0xFFFFFFFFull);
        smd[t]    = __ldcg(&g_dist[id * 128 + c]);
        sfs[t]    = __ldcg(&g_feat[id * 128 + c]);
        smf[t]    = __ldcg(&g_feat[jf * 128 + c]);
        smdist[t] = __ldcg(&g_dist[jf * 128 + c]);
    }
    __syncthreads();

    if (t < 256) sk1[t] = pk(smd[t], 255u - (unsigned)t);
    else { int c = t - 256; sk2[c] = pk(smf[c], 255u - (unsigned)c); }
    __syncthreads();

    // one warp per owned element (4 per block across 128 blocks = 512 total)
    if (w < 4) {
        int e = 4 * i + w;
        const unsigned long long* keys = (e < 256) ? sk1 : sk2;
        int c = (e < 256) ? e : (e - 256);
        unsigned long long mykey = keys[c];
        int cnt = 0;
#pragma unroll
        for (int jj = 0; jj < 8; jj++)
            cnt += (keys[jj * 32 + lane] > mykey) ? 1 : 0;
#pragma unroll
        for (int o = 16; o > 0; o >>= 1)
            cnt += __shfl_xor_sync(0xffffffffu, cnt, o);
        if (lane == 0) {
            if (e < 256) g_geo[cnt]       = smd[c] * sfs[c];
            else         g_geo[256 + cnt] = smdist[c] * smf[c];
        }
    }
    __syncthreads();

    // ===================== grid barrier #2 (geo ready) =====================
    if (t == 0) {
        bar_arrive(&g_ctr2);
        bar_spin(&g_ctr2, 128u);
    }
    __syncthreads();

    // colkeys consumed by all blocks in assemble above -> safe to reset
    if (t == 32) { g_colkey_d[i] = 0ull; g_colkey_f[i] = 0ull; }

    // ================= Phase 3: fc1, 2 channels per block ===================
    if (w < 2) {
        const float4* geo4 = reinterpret_cast<const float4*>(g_geo);
        float acc = 0.0f;
#pragma unroll
        for (int q = 0; q < 4; q++) {
            float4 a = sW1[w * 128 + lane + 32 * q];
            float4 g = __ldcg(&geo4[lane + 32 * q]);
            acc += a.x * g.x + a.y * g.y + a.z * g.z + a.w * g.w;
        }
#pragma unroll
        for (int o = 16; o > 0; o >>= 1)
            acc += __shfl_xor_sync(0xffffffffu, acc, o);
        if (lane == 0) g_h1[2 * i + w] = acc + sb_fc1[w];
    }
    __syncthreads();

    // ===================== grid barrier #3 (h1 ready) =====================
    if (t == 0) bar_arrive(&g_ctr3);
    if (i != 0) return;                       // non-zero blocks done
    if (t == 0) bar_spin(&g_ctr3, 128u);
    __syncthreads();

    // ============== Phase 4 (block 0): GN1+fc2+GN2+fc3 -> out ===============
    if (t < 256) {
        float x = __ldcg(&g_h1[t]);
        float s = x;
#pragma unroll
        for (int o = 16; o > 0; o >>= 1) s += __shfl_xor_sync(0xffffffffu, s, o);
        float mean = s * (1.0f / 32.0f);
        float ee = x - mean;
        float v = ee * ee;
#pragma unroll
        for (int o = 16; o > 0; o >>= 1) v += __shfl_xor_sync(0xffffffffu, v, o);
        v *= (1.0f / 32.0f);
        float xn = ee / sqrtf(v + 1e-5f) * sg1[t] + sb1g[t];
        sha[t] = fmaxf(xn, 0.0f);
    }
    __syncthreads();

    // fc2: 16 warps x 8 channels, W2 straight from L2
    {
        const float4* ha4 = reinterpret_cast<const float4*>(sha);
        float4 h0 = ha4[lane], h1v = ha4[lane + 32];
#pragma unroll 4
        for (int cc = 0; cc < 8; cc++) {
            int c = (w << 3) | cc;
            const float4* row = reinterpret_cast<const float4*>(W2 + (size_t)c * 256);
            float4 a0 = __ldg(&row[lane]);
            float4 a1 = __ldg(&row[lane + 32]);
            float acc = a0.x * h0.x + a0.y * h0.y + a0.z * h0.z + a0.w * h0.w
                      + a1.x * h1v.x + a1.y * h1v.y + a1.z * h1v.z + a1.w * h1v.w;
#pragma unroll
            for (int o = 16; o > 0; o >>= 1)
                acc += __shfl_xor_sync(0xffffffffu, acc, o);
            if (lane == 0) sh2[c] = acc + sb2[c];
        }
    }
    __syncthreads();

    // GN2 (8 groups x 16 = half-warp per group) + ReLU
    if (t < 128) {
        float x = sh2[t];
        float s = x;
#pragma unroll
        for (int o = 8; o > 0; o >>= 1) s += __shfl_xor_sync(0xffffffffu, s, o);
        float mean = s * (1.0f / 16.0f);
        float ee = x - mean;
        float v = ee * ee;
#pragma unroll
        for (int o = 8; o > 0; o >>= 1) v += __shfl_xor_sync(0xffffffffu, v, o);
        v *= (1.0f / 16.0f);
        float xn = ee / sqrtf(v + 1e-5f) * sg2[t] + sbt2[t];
        sh2a[t] = fmaxf(xn, 0.0f);
    }
    __syncthreads();

    // fc3: 128 -> 2
    if (w < 2) {
        float4 a = sW3[w * 32 + lane];
        float4 g = reinterpret_cast<const float4*>(sh2a)[lane];
        float acc = a.x * g.x + a.y * g.y + a.z * g.z + a.w * g.w;
#pragma unroll
        for (int o = 16; o > 0; o >>= 1)
            acc += __shfl_xor_sync(0xffffffffu, acc, o);
        if (lane == 0) out[w] = acc + sb3[w];
    }

    // reset barrier counters for next graph replay
    if (t == 0) { g_ctr1 = 0u; g_ctr2 = 0u; g_ctr3 = 0u; }
}

extern "C" void kernel_launch(void* const* d_in, const int* in_sizes, int n_in,
                              void* d_out, int out_size) {
    const float* pts   = (const float*)d_in[0];
    const float* reff  = (const float*)d_in[1];
    const float* srcf  = (const float*)d_in[2];
    const float* trans = (const float*)d_in[3];
    const float* W1  = (const float*)d_in[4];
    const float* b1  = (const float*)d_in[5];
    const float* g1  = (const float*)d_in[6];
    const float* bt1 = (const float*)d_in[7];
    const float* W2  = (const float*)d_in[8];
    const float* b2  = (const float*)d_in[9];
    const float* g2  = (const float*)d_in[10];
    const float* bt2 = (const float*)d_in[11];
    const float* W3  = (const float*)d_in[12];
    const float* b3  = (const float*)d_in[13];

    k_all<<<128, 512>>>(pts, trans, reff, srcf,
                        W1, b1, g1, bt1, W2, b2, g2, bt2, W3, b3,
                        (float*)d_out);
}